// round 4
// baseline (speedup 1.0000x reference)
#include <cuda_runtime.h>
#include <cstdint>

#define B_SZ   1024
#define T_SZ   16
#define IN_DIM 2048
#define DIM    1024
#define NACT   64

// ---------------- scratch (no allocations allowed) ----------------
__device__ float g_pavg[B_SZ * IN_DIM];     // 8 MB (tf32-rounded)
__device__ float g_eavg[B_SZ * IN_DIM];     // 8 MB (tf32-rounded)
__device__ float g_pembed[B_SZ * DIM];      // 4 MB (tf32-rounded)
__device__ int   g_counts[NACT];
__device__ int   g_cursor[NACT];            // group END after group_k
__device__ int   g_order[B_SZ];

// ---------------- helpers ----------------
__device__ __forceinline__ uint32_t f2tf32(float x) {
    uint32_t r;
    asm("cvt.rna.tf32.f32 %0, %1;" : "=r"(r) : "f"(x));
    return r;
}
__device__ __forceinline__ float f2tf32f(float x) { return __uint_as_float(f2tf32(x)); }

__device__ __forceinline__ void mma_tf32(float c[4], const uint32_t a[4], const uint32_t b[2]) {
    asm volatile(
        "mma.sync.aligned.m16n8k8.row.col.f32.tf32.tf32.f32 "
        "{%0,%1,%2,%3}, {%4,%5,%6,%7}, {%8,%9}, {%0,%1,%2,%3};"
        : "+f"(c[0]), "+f"(c[1]), "+f"(c[2]), "+f"(c[3])
        : "r"(a[0]), "r"(a[1]), "r"(a[2]), "r"(a[3]), "r"(b[0]), "r"(b[1]));
}

__device__ __forceinline__ void cpa16(float* dst, const float* src, uint32_t src_sz) {
    uint32_t d = (uint32_t)__cvta_generic_to_shared(dst);
    asm volatile("cp.async.ca.shared.global [%0], [%1], 16, %2;"
                 :: "r"(d), "l"(src), "r"(src_sz));
}
__device__ __forceinline__ void cpa_commit() { asm volatile("cp.async.commit_group;"); }
__device__ __forceinline__ void cpa_wait1()  { asm volatile("cp.async.wait_group 1;"); }
__device__ __forceinline__ void cpa_wait2()  { asm volatile("cp.async.wait_group 2;"); }

// ---------------- fused grouping: count + scan + scatter in ONE block ----------------
__global__ void group_k(const int* __restrict__ act) {
    __shared__ int s_cnt[NACT];
    __shared__ int s_base[NACT];
    const int tid = threadIdx.x;           // 1024 threads, one per batch
    if (tid < NACT) s_cnt[tid] = 0;
    __syncthreads();
    const int a = act[tid];
    atomicAdd(&s_cnt[a], 1);
    __syncthreads();
    if (tid == 0) {
        int run = 0;
        for (int i = 0; i < NACT; i++) { int c = s_cnt[i]; s_base[i] = run; run += c; }
    }
    __syncthreads();
    int pos = atomicAdd(&s_base[a], 1);
    g_order[pos] = tid;
    __syncthreads();
    if (tid < NACT) {
        g_counts[tid] = s_cnt[tid];
        g_cursor[tid] = s_base[tid];       // = group end
    }
}

// ---------------- time-mean (float4, tf32-rounded at store) ----------------
__global__ void mean_kernel(const float* __restrict__ pre, const float* __restrict__ eff) {
    const int idx = blockIdx.x * 256 + threadIdx.x;   // over B*IN/4
    const float4* src = (const float4*)(blockIdx.y ? eff : pre);
    float4*       dst = (float4*)(blockIdx.y ? g_eavg : g_pavg);
    const int b  = idx >> 9;               // / (IN_DIM/4)
    const int k4 = idx & 511;
    const float4* p = src + (size_t)b * T_SZ * (IN_DIM / 4) + k4;
    float4 s = make_float4(0.f, 0.f, 0.f, 0.f);
#pragma unroll
    for (int t = 0; t < T_SZ; t++) {
        float4 v = p[(size_t)t * (IN_DIM / 4)];
        s.x += v.x; s.y += v.y; s.z += v.z; s.w += v.w;
    }
    const float inv = 1.0f / T_SZ;
    dst[idx] = make_float4(f2tf32f(s.x * inv), f2tf32f(s.y * inv),
                           f2tf32f(s.z * inv), f2tf32f(s.w * inv));
}

// ---------------- embedding GEMM: C[1024x1024] = A[1024x2048] @ W^T + bias ----------------
// 128x128 tile, BK=32, 3-stage cp.async ring, 512 threads / 16 warps (4x4), warp tile 32x32.
#define G1_BM 128
#define G1_BN 128
#define G1_BK 32
#define SPAD  36
#define G1_NS 3
#define G1_SMEM (G1_NS * 2 * 128 * SPAD * 4)   // 110592 B

__global__ __launch_bounds__(512) void embed_gemm(
    const float* __restrict__ Wp, const float* __restrict__ bp,
    const float* __restrict__ We, const float* __restrict__ be,
    float* __restrict__ out_e)
{
    extern __shared__ float sm[];
    float* AsBase = sm;                         // [3][128][36]
    float* BsBase = sm + G1_NS * 128 * SPAD;    // [3][128][36]

    const float *A, *W, *bias;
    float* out;
    bool roundOut;
    if (blockIdx.z == 0) { A = g_pavg; W = Wp; bias = bp; out = g_pembed; roundOut = true;  }
    else                 { A = g_eavg; W = We; bias = be; out = out_e;    roundOut = false; }

    const int m0 = blockIdx.y * G1_BM;
    const int n0 = blockIdx.x * G1_BN;
    const int tid  = threadIdx.x;
    const int lane = tid & 31;
    const int warp = tid >> 5;                 // 0..15
    const int wm = (warp >> 2) * 32;           // 4 warp-rows over 128 M
    const int wn = (warp & 3) * 32;            // 4 warp-cols over 128 N

    const int lr = tid >> 3;                   // 0..63
    const int lc = (tid & 7) * 4;

    float acc[2][4][4];
#pragma unroll
    for (int i = 0; i < 2; i++)
#pragma unroll
        for (int j = 0; j < 4; j++)
#pragma unroll
            for (int r = 0; r < 4; r++) acc[i][j][r] = 0.f;

    const int NITER = IN_DIM / G1_BK;          // 64

    // prologue: stages 0,1
#pragma unroll
    for (int st = 0; st < G1_NS - 1; ++st) {
        const int k0 = st * G1_BK;
        float* Ab = AsBase + st * 128 * SPAD;
        float* Bb = BsBase + st * 128 * SPAD;
#pragma unroll
        for (int i = 0; i < 2; i++) {
            int r = lr + i * 64;
            cpa16(&Ab[r * SPAD + lc], A + (size_t)(m0 + r) * IN_DIM + k0 + lc, 16);
            cpa16(&Bb[r * SPAD + lc], W + (size_t)(n0 + r) * IN_DIM + k0 + lc, 16);
        }
        cpa_commit();
    }

    for (int it = 0; it < NITER; ++it) {
        cpa_wait1();                           // stage `it` complete
        __syncthreads();

        if (it + G1_NS - 1 < NITER) {
            const int st = it + G1_NS - 1;
            const int slot = st % G1_NS;
            const int k0 = st * G1_BK;
            float* Ab = AsBase + slot * 128 * SPAD;
            float* Bb = BsBase + slot * 128 * SPAD;
#pragma unroll
            for (int i = 0; i < 2; i++) {
                int r = lr + i * 64;
                cpa16(&Ab[r * SPAD + lc], A + (size_t)(m0 + r) * IN_DIM + k0 + lc, 16);
                cpa16(&Bb[r * SPAD + lc], W + (size_t)(n0 + r) * IN_DIM + k0 + lc, 16);
            }
            cpa_commit();
        } else {
            cpa_commit();
        }

        const int buf = it % G1_NS;
        const float* Ab = AsBase + buf * 128 * SPAD;
        const float* Bb = BsBase + buf * 128 * SPAD;

#pragma unroll
        for (int kk = 0; kk < G1_BK; kk += 8) {
            uint32_t af[2][4], bf[4][2];
#pragma unroll
            for (int ms = 0; ms < 2; ms++) {
                int r  = wm + ms * 16 + (lane >> 2);
                int cA = kk + (lane & 3);
                af[ms][0] = __float_as_uint(Ab[r * SPAD + cA]);         // pre-rounded
                af[ms][1] = __float_as_uint(Ab[(r + 8) * SPAD + cA]);
                af[ms][2] = __float_as_uint(Ab[r * SPAD + cA + 4]);
                af[ms][3] = __float_as_uint(Ab[(r + 8) * SPAD + cA + 4]);
            }
#pragma unroll
            for (int ns = 0; ns < 4; ns++) {
                int n  = wn + ns * 8 + (lane >> 2);
                int ck = kk + (lane & 3);
                bf[ns][0] = f2tf32(Bb[n * SPAD + ck]);                  // raw W: cvt here
                bf[ns][1] = f2tf32(Bb[n * SPAD + ck + 4]);
            }
#pragma unroll
            for (int ms = 0; ms < 2; ms++)
#pragma unroll
                for (int ns = 0; ns < 4; ns++)
                    mma_tf32(acc[ms][ns], af[ms], bf[ns]);
        }
        __syncthreads();
    }

    // epilogue: + bias (round to tf32 only for the p path, which feeds GEMM2)
#pragma unroll
    for (int ns = 0; ns < 4; ns++) {
        int c0 = n0 + wn + ns * 8 + 2 * (lane & 3);
        float b0v = bias[c0];
        float b1v = bias[c0 + 1];
#pragma unroll
        for (int ms = 0; ms < 2; ms++) {
            int r0 = m0 + wm + ms * 16 + (lane >> 2);
            float2 lo = make_float2(acc[ms][ns][0] + b0v, acc[ms][ns][1] + b1v);
            float2 hi = make_float2(acc[ms][ns][2] + b0v, acc[ms][ns][3] + b1v);
            if (roundOut) {
                lo.x = f2tf32f(lo.x); lo.y = f2tf32f(lo.y);
                hi.x = f2tf32f(hi.x); hi.y = f2tf32f(hi.y);
            }
            *(float2*)(out + (size_t)r0 * DIM + c0)       = lo;
            *(float2*)(out + (size_t)(r0 + 8) * DIM + c0) = hi;
        }
    }
}

// ---------------- grouped transform: p_t[b,i] = sum_j Wt[a_b][i][j] * p_embed[b][j] ----------------
// 4-stage cp.async ring keeps 2-3 W stages (32-48 KB) in flight per block.
#define T_BM 32
#define T_BN 128
#define T_BK 32
#define T_NS 4
#define T_SMEM ((T_NS * T_BM * SPAD + T_NS * T_BN * SPAD) * 4)   // 92160 B

__global__ __launch_bounds__(256) void trans_gemm(const float* __restrict__ Wt,
                                                  float* __restrict__ out)
{
    const int a     = blockIdx.y;
    const int cnt   = g_counts[a];
    const int chunk = blockIdx.z;
    if (chunk * T_BM >= cnt) return;

    const int start  = g_cursor[a] - cnt + chunk * T_BM;
    const int nvalid = min(T_BM, cnt - chunk * T_BM);

    __shared__ int s_ord[T_BM];
    extern __shared__ float tsm[];
    float* As = tsm;                       // [4][32][SPAD]
    float* Bs = tsm + T_NS * T_BM * SPAD;  // [4][128][SPAD]

    const int tid  = threadIdx.x;
    const int lane = tid & 31;
    const int warp = tid >> 5;
    const int wm = (warp >> 2) * 16;   // 2 warp-rows over 32 batches
    const int wn = (warp & 3) * 32;    // 4 warp-cols over 128 dims
    const int i0 = blockIdx.x * T_BN;

    if (tid < T_BM) s_ord[tid] = (tid < nvalid) ? g_order[start + tid] : -1;
    __syncthreads();

    const float* Wa = Wt + (size_t)a * DIM * DIM;

    const int lrA = tid >> 3;          // 0..31
    const int lc  = (tid & 7) * 4;
    const int bA  = s_ord[lrA];
    const float* srcA0 = (bA >= 0) ? g_pembed + (size_t)bA * DIM + lc : g_pembed;
    const uint32_t szA = (bA >= 0) ? 16u : 0u;

    float acc[4][4];
#pragma unroll
    for (int j = 0; j < 4; j++)
#pragma unroll
        for (int r = 0; r < 4; r++) acc[j][r] = 0.f;

    const int NITER = DIM / T_BK;      // 32

    // prologue: stages 0..2
#pragma unroll
    for (int st = 0; st < T_NS - 1; ++st) {
        const int k0 = st * T_BK;
        cpa16(&As[st * T_BM * SPAD + lrA * SPAD + lc], srcA0 + (szA ? k0 : 0), szA);
#pragma unroll
        for (int i = 0; i < 4; i++) {
            int r = lrA + i * 32;
            cpa16(&Bs[st * T_BN * SPAD + r * SPAD + lc],
                  Wa + (size_t)(i0 + r) * DIM + k0 + lc, 16);
        }
        cpa_commit();
    }

    for (int it = 0; it < NITER; ++it) {
        cpa_wait2();                   // stage `it` guaranteed complete
        __syncthreads();

        if (it + T_NS - 1 < NITER) {
            const int st = it + T_NS - 1;
            const int slot = st & (T_NS - 1);
            const int k0 = st * T_BK;
            cpa16(&As[slot * T_BM * SPAD + lrA * SPAD + lc], srcA0 + (szA ? k0 : 0), szA);
#pragma unroll
            for (int i = 0; i < 4; i++) {
                int r = lrA + i * 32;
                cpa16(&Bs[slot * T_BN * SPAD + r * SPAD + lc],
                      Wa + (size_t)(i0 + r) * DIM + k0 + lc, 16);
            }
            cpa_commit();
        } else {
            cpa_commit();              // empty group keeps wait_group bookkeeping correct
        }

        const int buf = it & (T_NS - 1);
        const float* Ab = As + buf * T_BM * SPAD;
        const float* Bb = Bs + buf * T_BN * SPAD;

#pragma unroll
        for (int kk = 0; kk < T_BK; kk += 8) {
            uint32_t af[4], bf[4][2];
            {
                int r  = wm + (lane >> 2);
                int cA = kk + (lane & 3);
                af[0] = __float_as_uint(Ab[r * SPAD + cA]);        // pre-rounded
                af[1] = __float_as_uint(Ab[(r + 8) * SPAD + cA]);
                af[2] = __float_as_uint(Ab[r * SPAD + cA + 4]);
                af[3] = __float_as_uint(Ab[(r + 8) * SPAD + cA + 4]);
            }
#pragma unroll
            for (int ns = 0; ns < 4; ns++) {
                int n  = wn + ns * 8 + (lane >> 2);
                int ck = kk + (lane & 3);
                bf[ns][0] = f2tf32(Bb[n * SPAD + ck]);             // W_trans: cvt here
                bf[ns][1] = f2tf32(Bb[n * SPAD + ck + 4]);
            }
#pragma unroll
            for (int ns = 0; ns < 4; ns++)
                mma_tf32(acc[ns], af, bf[ns]);
        }
        __syncthreads();
    }

    // epilogue: scatter to out[b*DIM + i]
    const int rA = wm + (lane >> 2);
    const int b0 = s_ord[rA];
    const int b1 = s_ord[rA + 8];
#pragma unroll
    for (int ns = 0; ns < 4; ns++) {
        int c0 = i0 + wn + ns * 8 + 2 * (lane & 3);
        if (b0 >= 0)
            *(float2*)(out + (size_t)b0 * DIM + c0) = make_float2(acc[ns][0], acc[ns][1]);
        if (b1 >= 0)
            *(float2*)(out + (size_t)b1 * DIM + c0) = make_float2(acc[ns][2], acc[ns][3]);
    }
}

// ---------------- launch ----------------
extern "C" void kernel_launch(void* const* d_in, const int* in_sizes, int n_in,
                              void* d_out, int out_size)
{
    const float* pre = (const float*)d_in[0];
    const float* eff = (const float*)d_in[1];
    const int*   act = (const int*)d_in[2];
    const float* Wp  = (const float*)d_in[3];
    const float* bp  = (const float*)d_in[4];
    const float* We  = (const float*)d_in[5];
    const float* be  = (const float*)d_in[6];
    const float* Wt  = (const float*)d_in[7];

    float* out   = (float*)d_out;              // p_transformed: (B,1,DIM,1)
    float* out_e = out + (size_t)B_SZ * DIM;   // e_embed: (B,DIM)

    cudaFuncSetAttribute(embed_gemm, cudaFuncAttributeMaxDynamicSharedMemorySize, G1_SMEM);
    cudaFuncSetAttribute(trans_gemm, cudaFuncAttributeMaxDynamicSharedMemorySize, T_SMEM);

    group_k<<<1, B_SZ>>>(act);

    mean_kernel<<<dim3(B_SZ * IN_DIM / 4 / 256, 2), 256>>>(pre, eff);

    embed_gemm<<<dim3(DIM / G1_BN, DIM / G1_BM, 2), 512, G1_SMEM>>>(Wp, bp, We, be, out_e);

    trans_gemm<<<dim3(DIM / T_BN, NACT, B_SZ / T_BM), 256, T_SMEM>>>(Wt, out);
}

// round 6
// speedup vs baseline: 1.3472x; 1.3472x over previous
#include <cuda_runtime.h>
#include <cuda_fp16.h>
#include <cstdint>

#define B_SZ   1024
#define T_SZ   16
#define IN_DIM 2048
#define DIM    1024
#define NACT   64

// ---------------- scratch (no allocations allowed) ----------------
__device__ __align__(16) __half g_pavg_h[B_SZ * IN_DIM];   // 4 MB fp16 means
__device__ __align__(16) __half g_eavg_h[B_SZ * IN_DIM];   // 4 MB
__device__ __align__(16) __half g_wph[DIM * IN_DIM];       // 4 MB fp16 Wp
__device__ __align__(16) __half g_weh[DIM * IN_DIM];       // 4 MB fp16 We
__device__ __align__(16) __half g_pembed_h[B_SZ * DIM];    // 2 MB fp16 p_embed
__device__ int   g_counts[NACT];
__device__ int   g_cursor[NACT];            // group END after group_k
__device__ int   g_order[B_SZ];

// ---------------- helpers ----------------
__device__ __forceinline__ uint32_t packf16(float lo, float hi) {
    uint32_t r;
    asm("cvt.rn.f16x2.f32 %0, %1, %2;" : "=r"(r) : "f"(hi), "f"(lo));
    return r;
}

__device__ __forceinline__ void mma_f16(float c[4], const uint32_t a[4], const uint32_t b[2]) {
    asm volatile(
        "mma.sync.aligned.m16n8k16.row.col.f32.f16.f16.f32 "
        "{%0,%1,%2,%3}, {%4,%5,%6,%7}, {%8,%9}, {%0,%1,%2,%3};"
        : "+f"(c[0]), "+f"(c[1]), "+f"(c[2]), "+f"(c[3])
        : "r"(a[0]), "r"(a[1]), "r"(a[2]), "r"(a[3]), "r"(b[0]), "r"(b[1]));
}

__device__ __forceinline__ void cpa16(void* dst, const void* src, uint32_t src_sz) {
    uint32_t d = (uint32_t)__cvta_generic_to_shared(dst);
    asm volatile("cp.async.ca.shared.global [%0], [%1], 16, %2;"
                 :: "r"(d), "l"(src), "r"(src_sz));
}
__device__ __forceinline__ void cpa_commit() { asm volatile("cp.async.commit_group;"); }
__device__ __forceinline__ void cpa_wait0()  { asm volatile("cp.async.wait_group 0;"); }
__device__ __forceinline__ void cpa_wait2()  { asm volatile("cp.async.wait_group 2;"); }

// ---------------- fused grouping: count + scan + scatter in ONE block ----------------
__global__ void group_k(const int* __restrict__ act) {
    __shared__ int s_cnt[NACT];
    __shared__ int s_base[NACT];
    const int tid = threadIdx.x;           // 1024 threads, one per batch
    if (tid < NACT) s_cnt[tid] = 0;
    __syncthreads();
    const int a = act[tid];
    atomicAdd(&s_cnt[a], 1);
    __syncthreads();
    if (tid == 0) {
        int run = 0;
        for (int i = 0; i < NACT; i++) { int c = s_cnt[i]; s_base[i] = run; run += c; }
    }
    __syncthreads();
    int pos = atomicAdd(&s_base[a], 1);
    g_order[pos] = tid;
    __syncthreads();
    if (tid < NACT) {
        g_counts[tid] = s_cnt[tid];
        g_cursor[tid] = s_base[tid];       // = group end
    }
}

// ---------------- time-mean -> fp16 ----------------
__global__ void mean_kernel(const float* __restrict__ pre, const float* __restrict__ eff) {
    const int idx = blockIdx.x * 256 + threadIdx.x;   // over B*IN/4
    const float4* src = (const float4*)(blockIdx.y ? eff : pre);
    __half*       dst = blockIdx.y ? g_eavg_h : g_pavg_h;
    const int b  = idx >> 9;
    const int k4 = idx & 511;
    const float4* p = src + (size_t)b * T_SZ * (IN_DIM / 4) + k4;
    float4 s = make_float4(0.f, 0.f, 0.f, 0.f);
#pragma unroll
    for (int t = 0; t < T_SZ; t++) {
        float4 v = p[(size_t)t * (IN_DIM / 4)];
        s.x += v.x; s.y += v.y; s.z += v.z; s.w += v.w;
    }
    const float inv = 1.0f / T_SZ;
    uint2 o;
    o.x = packf16(s.x * inv, s.y * inv);
    o.y = packf16(s.z * inv, s.w * inv);
    *(uint2*)(dst + (size_t)idx * 4) = o;
}

// ---------------- convert Wp/We -> fp16 ----------------
__global__ void wconv_k(const float* __restrict__ Wp, const float* __restrict__ We) {
    const int half_n = DIM * IN_DIM / 4;
    int idx = blockIdx.x * 256 + threadIdx.x;
    const float4* src;
    __half* dst;
    int j;
    if (idx < half_n) { src = (const float4*)Wp; dst = g_wph; j = idx; }
    else              { src = (const float4*)We; dst = g_weh; j = idx - half_n; }
    float4 v = src[j];
    uint2 o;
    o.x = packf16(v.x, v.y);
    o.y = packf16(v.z, v.w);
    *(uint2*)(dst + (size_t)j * 4) = o;
}

// ---------------- embedding GEMM (fp16 MMA): C[1024x1024] = A @ W^T + bias ----------------
// 64x128 tile, BK=64 halves (128B rows), 2-stage cp.async, 8 warps 2(M)x4(N), warp 32x32.
#define G1_BM 64
#define G1_BN 128
#define G1_BK 64
#define G1_AS 72                       // A/B smem row stride in halves (144B: conflict-free)
#define G1_STG_A (G1_BM * G1_AS)       // halves per A stage
#define G1_STG_B (G1_BN * G1_AS)
#define G1_SMEM ((2 * (G1_STG_A + G1_STG_B)) * 2)   // 55296 B

__global__ __launch_bounds__(256) void embed_gemm(
    const float* __restrict__ bp, const float* __restrict__ be,
    float* __restrict__ out_e)
{
    extern __shared__ __half esm[];
    __half* AsBase = esm;                         // [2][64][72]
    __half* BsBase = esm + 2 * G1_STG_A;          // [2][128][72]

    const __half *A, *W;
    const float* bias;
    const bool isP = (blockIdx.z == 0);
    if (isP) { A = g_pavg_h; W = g_wph; bias = bp; }
    else     { A = g_eavg_h; W = g_weh; bias = be; }

    const int m0 = blockIdx.y * G1_BM;
    const int n0 = blockIdx.x * G1_BN;
    const int tid  = threadIdx.x;
    const int lane = tid & 31;
    const int warp = tid >> 5;
    const int wm = (warp >> 2) * 32;   // 2 warp-rows over 64 M
    const int wn = (warp & 3) * 32;    // 4 warp-cols over 128 N

    float acc[2][4][4];
#pragma unroll
    for (int i = 0; i < 2; i++)
#pragma unroll
        for (int j = 0; j < 4; j++)
#pragma unroll
            for (int r = 0; r < 4; r++) acc[i][j][r] = 0.f;

    const int lr = tid >> 3;           // 0..31
    const int lc = (tid & 7) * 8;      // halves within 64-col tile

    // prologue: stage 0
    {
#pragma unroll
        for (int i = 0; i < 2; i++) {   // A: 64 rows
            int r = lr + i * 32;
            cpa16(AsBase + r * G1_AS + lc, A + (size_t)(m0 + r) * IN_DIM + lc, 16);
        }
#pragma unroll
        for (int i = 0; i < 4; i++) {   // B: 128 rows
            int r = lr + i * 32;
            cpa16(BsBase + r * G1_AS + lc, W + (size_t)(n0 + r) * IN_DIM + lc, 16);
        }
        cpa_commit();
    }

    const int NITER = IN_DIM / G1_BK;  // 32
    for (int it = 0; it < NITER; ++it) {
        cpa_wait0();
        __syncthreads();

        if (it + 1 < NITER) {
            const int k0 = (it + 1) * G1_BK;
            __half* Ab = AsBase + ((it + 1) & 1) * G1_STG_A;
            __half* Bb = BsBase + ((it + 1) & 1) * G1_STG_B;
#pragma unroll
            for (int i = 0; i < 2; i++) {
                int r = lr + i * 32;
                cpa16(Ab + r * G1_AS + lc, A + (size_t)(m0 + r) * IN_DIM + k0 + lc, 16);
            }
#pragma unroll
            for (int i = 0; i < 4; i++) {
                int r = lr + i * 32;
                cpa16(Bb + r * G1_AS + lc, W + (size_t)(n0 + r) * IN_DIM + k0 + lc, 16);
            }
            cpa_commit();
        }

        const __half* Ab = AsBase + (it & 1) * G1_STG_A;
        const __half* Bb = BsBase + (it & 1) * G1_STG_B;

#pragma unroll
        for (int kk = 0; kk < G1_BK; kk += 16) {
            uint32_t af[2][4], bf[4][2];
            const int q2 = 2 * (lane & 3);
#pragma unroll
            for (int ms = 0; ms < 2; ms++) {
                int r = wm + ms * 16 + (lane >> 2);
                af[ms][0] = *(const uint32_t*)(Ab + r * G1_AS + kk + q2);
                af[ms][1] = *(const uint32_t*)(Ab + (r + 8) * G1_AS + kk + q2);
                af[ms][2] = *(const uint32_t*)(Ab + r * G1_AS + kk + 8 + q2);
                af[ms][3] = *(const uint32_t*)(Ab + (r + 8) * G1_AS + kk + 8 + q2);
            }
#pragma unroll
            for (int ns = 0; ns < 4; ns++) {
                int n = wn + ns * 8 + (lane >> 2);
                bf[ns][0] = *(const uint32_t*)(Bb + n * G1_AS + kk + q2);
                bf[ns][1] = *(const uint32_t*)(Bb + n * G1_AS + kk + 8 + q2);
            }
#pragma unroll
            for (int ms = 0; ms < 2; ms++)
#pragma unroll
                for (int ns = 0; ns < 4; ns++)
                    mma_f16(acc[ms][ns], af[ms], bf[ns]);
        }
        __syncthreads();
    }

    // epilogue: + bias. p path -> fp16 g_pembed_h; e path -> fp32 out_e.
#pragma unroll
    for (int ns = 0; ns < 4; ns++) {
        int c0 = n0 + wn + ns * 8 + 2 * (lane & 3);
        float b0v = bias[c0];
        float b1v = bias[c0 + 1];
#pragma unroll
        for (int ms = 0; ms < 2; ms++) {
            int r0 = m0 + wm + ms * 16 + (lane >> 2);
            float2 lo = make_float2(acc[ms][ns][0] + b0v, acc[ms][ns][1] + b1v);
            float2 hi = make_float2(acc[ms][ns][2] + b0v, acc[ms][ns][3] + b1v);
            if (isP) {
                *(uint32_t*)(g_pembed_h + (size_t)r0 * DIM + c0)       = packf16(lo.x, lo.y);
                *(uint32_t*)(g_pembed_h + (size_t)(r0 + 8) * DIM + c0) = packf16(hi.x, hi.y);
            } else {
                *(float2*)(out_e + (size_t)r0 * DIM + c0)       = lo;
                *(float2*)(out_e + (size_t)(r0 + 8) * DIM + c0) = hi;
            }
        }
    }
}

// ---------------- grouped transform (fp16 MMA, W_trans fp32 cvt in-loop) ----------------
// p_t[b,i] = sum_j Wt[a_b][i][j] * p_embed[b][j]
#define T_BM 32
#define T_BN 128
#define T_BK 32
#define T_NS 4
#define T_ASTR 40   // A smem row stride in halves (80B)
#define T_BSTR 40   // B smem row stride in floats (160B: conflict-free float2)
#define T_STG_A (T_BM * T_ASTR)            // halves
#define T_STG_B (T_BN * T_BSTR)            // floats
#define T_SMEM (T_NS * (T_STG_A * 2 + T_STG_B * 4))   // 92160 B

__global__ __launch_bounds__(256) void trans_gemm(const float* __restrict__ Wt,
                                                  float* __restrict__ out)
{
    const int a     = blockIdx.y;
    const int cnt   = g_counts[a];
    const int chunk = blockIdx.z;
    if (chunk * T_BM >= cnt) return;

    const int start  = g_cursor[a] - cnt + chunk * T_BM;
    const int nvalid = min(T_BM, cnt - chunk * T_BM);

    __shared__ int s_ord[T_BM];
    extern __shared__ char tsm[];
    __half* As = (__half*)tsm;                         // [4][32][40]
    float*  Bs = (float*)(tsm + T_NS * T_STG_A * 2);   // [4][128][40]

    const int tid  = threadIdx.x;
    const int lane = tid & 31;
    const int warp = tid >> 5;
    const int wm = (warp >> 2) * 16;   // 2 warp-rows over 32 batches
    const int wn = (warp & 3) * 32;    // 4 warp-cols over 128 dims
    const int i0 = blockIdx.x * T_BN;

    if (tid < T_BM) s_ord[tid] = (tid < nvalid) ? g_order[start + tid] : -1;
    __syncthreads();

    const float* Wa = Wt + (size_t)a * DIM * DIM;

    // A loader: threads 0..127, each owns (row=tid>>2, chunk=(tid&3)*8 halves)
    const int  arow = tid >> 2;
    const int  ach  = (tid & 3) * 8;
    const int  bA   = (tid < 128) ? s_ord[arow] : -1;
    const __half*  srcA0 = (bA >= 0) ? g_pembed_h + (size_t)bA * DIM + ach : g_pembed_h;
    const uint32_t szA   = (bA >= 0) ? 16u : 0u;

    float acc[4][4];
#pragma unroll
    for (int j = 0; j < 4; j++)
#pragma unroll
        for (int r = 0; r < 4; r++) acc[j][r] = 0.f;

    const int NITER = DIM / T_BK;      // 32

    // prologue: stages 0..2
#pragma unroll
    for (int st = 0; st < T_NS - 1; ++st) {
        const int k0 = st * T_BK;
        if (tid < 128)
            cpa16(As + st * T_STG_A + arow * T_ASTR + ach, srcA0 + (szA ? k0 : 0), szA);
#pragma unroll
        for (int i = 0; i < 4; i++) {
            int idx = tid + i * 256;
            int r = idx >> 3, c = (idx & 7) * 4;
            cpa16(Bs + st * T_STG_B + r * T_BSTR + c,
                  Wa + (size_t)(i0 + r) * DIM + k0 + c, 16);
        }
        cpa_commit();
    }

    for (int it = 0; it < NITER; ++it) {
        cpa_wait2();
        __syncthreads();

        if (it + T_NS - 1 < NITER) {
            const int st = it + T_NS - 1;
            const int slot = st & (T_NS - 1);
            const int k0 = st * T_BK;
            if (tid < 128)
                cpa16(As + slot * T_STG_A + arow * T_ASTR + ach, srcA0 + (szA ? k0 : 0), szA);
#pragma unroll
            for (int i = 0; i < 4; i++) {
                int idx = tid + i * 256;
                int r = idx >> 3, c = (idx & 7) * 4;
                cpa16(Bs + slot * T_STG_B + r * T_BSTR + c,
                      Wa + (size_t)(i0 + r) * DIM + k0 + c, 16);
            }
            cpa_commit();
        } else {
            cpa_commit();
        }

        const int buf = it & (T_NS - 1);
        const __half* Ab = As + buf * T_STG_A;
        const float*  Bb = Bs + buf * T_STG_B;
        const int q2 = 2 * (lane & 3);

#pragma unroll
        for (int kk = 0; kk < T_BK; kk += 16) {
            uint32_t af[4], bf[4][2];
            {
                int r = wm + (lane >> 2);
                af[0] = *(const uint32_t*)(Ab + r * T_ASTR + kk + q2);
                af[1] = *(const uint32_t*)(Ab + (r + 8) * T_ASTR + kk + q2);
                af[2] = *(const uint32_t*)(Ab + r * T_ASTR + kk + 8 + q2);
                af[3] = *(const uint32_t*)(Ab + (r + 8) * T_ASTR + kk + 8 + q2);
            }
#pragma unroll
            for (int ns = 0; ns < 4; ns++) {
                int n = wn + ns * 8 + (lane >> 2);
                float2 v0 = *(const float2*)(Bb + n * T_BSTR + kk + q2);
                float2 v1 = *(const float2*)(Bb + n * T_BSTR + kk + 8 + q2);
                bf[ns][0] = packf16(v0.x, v0.y);
                bf[ns][1] = packf16(v1.x, v1.y);
            }
#pragma unroll
            for (int ns = 0; ns < 4; ns++)
                mma_f16(acc[ns], af, bf[ns]);
        }
        __syncthreads();
    }

    // epilogue: scatter to out[b*DIM + i]
    const int rA = wm + (lane >> 2);
    const int b0 = s_ord[rA];
    const int b1 = s_ord[rA + 8];
#pragma unroll
    for (int ns = 0; ns < 4; ns++) {
        int c0 = i0 + wn + ns * 8 + 2 * (lane & 3);
        if (b0 >= 0)
            *(float2*)(out + (size_t)b0 * DIM + c0) = make_float2(acc[ns][0], acc[ns][1]);
        if (b1 >= 0)
            *(float2*)(out + (size_t)b1 * DIM + c0) = make_float2(acc[ns][2], acc[ns][3]);
    }
}

// ---------------- launch ----------------
extern "C" void kernel_launch(void* const* d_in, const int* in_sizes, int n_in,
                              void* d_out, int out_size)
{
    const float* pre = (const float*)d_in[0];
    const float* eff = (const float*)d_in[1];
    const int*   act = (const int*)d_in[2];
    const float* Wp  = (const float*)d_in[3];
    const float* bp  = (const float*)d_in[4];
    const float* We  = (const float*)d_in[5];
    const float* be  = (const float*)d_in[6];
    const float* Wt  = (const float*)d_in[7];

    float* out   = (float*)d_out;              // p_transformed: (B,1,DIM,1)
    float* out_e = out + (size_t)B_SZ * DIM;   // e_embed: (B,DIM)

    cudaFuncSetAttribute(embed_gemm, cudaFuncAttributeMaxDynamicSharedMemorySize, G1_SMEM);
    cudaFuncSetAttribute(trans_gemm, cudaFuncAttributeMaxDynamicSharedMemorySize, T_SMEM);

    group_k<<<1, B_SZ>>>(act);

    wconv_k<<<2 * DIM * IN_DIM / 4 / 256, 256>>>(Wp, We);

    mean_kernel<<<dim3(B_SZ * IN_DIM / 4 / 256, 2), 256>>>(pre, eff);

    embed_gemm<<<dim3(DIM / G1_BN, DIM / G1_BM, 2), 256, G1_SMEM>>>(bp, be, out_e);

    trans_gemm<<<dim3(DIM / T_BN, NACT, B_SZ / T_BM), 256, T_SMEM>>>(Wt, out);
}

// round 7
// speedup vs baseline: 1.4025x; 1.0411x over previous
#include <cuda_runtime.h>
#include <cuda_fp16.h>
#include <cstdint>

#define B_SZ   1024
#define T_SZ   16
#define IN_DIM 2048
#define DIM    1024
#define NACT   64

// ---------------- scratch (no allocations allowed) ----------------
__device__ __align__(16) __half g_pavg_h[B_SZ * IN_DIM];   // 4 MB fp16 means
__device__ __align__(16) __half g_eavg_h[B_SZ * IN_DIM];   // 4 MB
__device__ __align__(16) __half g_wph[DIM * IN_DIM];       // 4 MB fp16 Wp
__device__ __align__(16) __half g_weh[DIM * IN_DIM];       // 4 MB fp16 We
__device__ __align__(16) __half g_pembed_h[B_SZ * DIM];    // 2 MB fp16 p_embed
__device__ int   g_counts[NACT];
__device__ int   g_cursor[NACT];            // group END after group_k
__device__ int   g_order[B_SZ];

// ---------------- helpers ----------------
__device__ __forceinline__ uint32_t packf16(float lo, float hi) {
    uint32_t r;
    asm("cvt.rn.f16x2.f32 %0, %1, %2;" : "=r"(r) : "f"(hi), "f"(lo));
    return r;
}

__device__ __forceinline__ void mma_f16(float c[4], const uint32_t a[4], const uint32_t b[2]) {
    asm volatile(
        "mma.sync.aligned.m16n8k16.row.col.f32.f16.f16.f32 "
        "{%0,%1,%2,%3}, {%4,%5,%6,%7}, {%8,%9}, {%0,%1,%2,%3};"
        : "+f"(c[0]), "+f"(c[1]), "+f"(c[2]), "+f"(c[3])
        : "r"(a[0]), "r"(a[1]), "r"(a[2]), "r"(a[3]), "r"(b[0]), "r"(b[1]));
}

__device__ __forceinline__ void ldsm_x4(uint32_t& r0, uint32_t& r1, uint32_t& r2, uint32_t& r3,
                                        const void* p) {
    uint32_t a = (uint32_t)__cvta_generic_to_shared(p);
    asm volatile("ldmatrix.sync.aligned.m8n8.x4.shared.b16 {%0,%1,%2,%3}, [%4];"
                 : "=r"(r0), "=r"(r1), "=r"(r2), "=r"(r3) : "r"(a));
}

__device__ __forceinline__ void cpa16(void* dst, const void* src, uint32_t src_sz) {
    uint32_t d = (uint32_t)__cvta_generic_to_shared(dst);
    asm volatile("cp.async.ca.shared.global [%0], [%1], 16, %2;"
                 :: "r"(d), "l"(src), "r"(src_sz));
}
__device__ __forceinline__ void cpa_commit() { asm volatile("cp.async.commit_group;"); }
__device__ __forceinline__ void cpa_wait1()  { asm volatile("cp.async.wait_group 1;"); }
__device__ __forceinline__ void cpa_wait2()  { asm volatile("cp.async.wait_group 2;"); }

// ---------------- fused grouping: count + scan + scatter in ONE block ----------------
__global__ void group_k(const int* __restrict__ act) {
    __shared__ int s_cnt[NACT];
    __shared__ int s_base[NACT];
    const int tid = threadIdx.x;           // 1024 threads, one per batch
    if (tid < NACT) s_cnt[tid] = 0;
    __syncthreads();
    const int a = act[tid];
    atomicAdd(&s_cnt[a], 1);
    __syncthreads();
    if (tid == 0) {
        int run = 0;
        for (int i = 0; i < NACT; i++) { int c = s_cnt[i]; s_base[i] = run; run += c; }
    }
    __syncthreads();
    int pos = atomicAdd(&s_base[a], 1);
    g_order[pos] = tid;
    __syncthreads();
    if (tid < NACT) {
        g_counts[tid] = s_cnt[tid];
        g_cursor[tid] = s_base[tid];       // = group end
    }
}

// ---------------- time-mean -> fp16 ----------------
__global__ void mean_kernel(const float* __restrict__ pre, const float* __restrict__ eff) {
    const int idx = blockIdx.x * 256 + threadIdx.x;   // over B*IN/4
    const float4* src = (const float4*)(blockIdx.y ? eff : pre);
    __half*       dst = blockIdx.y ? g_eavg_h : g_pavg_h;
    const int b  = idx >> 9;
    const int k4 = idx & 511;
    const float4* p = src + (size_t)b * T_SZ * (IN_DIM / 4) + k4;
    float4 s = make_float4(0.f, 0.f, 0.f, 0.f);
#pragma unroll
    for (int t = 0; t < T_SZ; t++) {
        float4 v = p[(size_t)t * (IN_DIM / 4)];
        s.x += v.x; s.y += v.y; s.z += v.z; s.w += v.w;
    }
    const float inv = 1.0f / T_SZ;
    uint2 o;
    o.x = packf16(s.x * inv, s.y * inv);
    o.y = packf16(s.z * inv, s.w * inv);
    *(uint2*)(dst + (size_t)idx * 4) = o;
}

// ---------------- convert Wp/We -> fp16 ----------------
__global__ void wconv_k(const float* __restrict__ Wp, const float* __restrict__ We) {
    const int half_n = DIM * IN_DIM / 4;
    int idx = blockIdx.x * 256 + threadIdx.x;
    const float4* src;
    __half* dst;
    int j;
    if (idx < half_n) { src = (const float4*)Wp; dst = g_wph; j = idx; }
    else              { src = (const float4*)We; dst = g_weh; j = idx - half_n; }
    float4 v = src[j];
    uint2 o;
    o.x = packf16(v.x, v.y);
    o.y = packf16(v.z, v.w);
    *(uint2*)(dst + (size_t)j * 4) = o;
}

// ---------------- embedding GEMM (fp16 MMA + ldmatrix): C = A @ W^T + bias ----------------
// 64x128 tile, BK=64 halves, 3-stage cp.async ring, 8 warps 2(M)x4(N), warp 32x32.
#define G1_BM 64
#define G1_BN 128
#define G1_BK 64
#define G1_AS 72                       // smem row stride in halves (144B: LDSM conflict-free)
#define G1_STG_A (G1_BM * G1_AS)       // halves per A stage
#define G1_STG_B (G1_BN * G1_AS)
#define G1_NS 3
#define G1_SMEM ((G1_NS * (G1_STG_A + G1_STG_B)) * 2)   // 82944 B

__global__ __launch_bounds__(256) void embed_gemm(
    const float* __restrict__ bp, const float* __restrict__ be,
    float* __restrict__ out_e)
{
    extern __shared__ __half esm[];
    __half* AsBase = esm;                             // [3][64][72]
    __half* BsBase = esm + G1_NS * G1_STG_A;          // [3][128][72]

    const __half *A, *W;
    const float* bias;
    const bool isP = (blockIdx.z == 0);
    if (isP) { A = g_pavg_h; W = g_wph; bias = bp; }
    else     { A = g_eavg_h; W = g_weh; bias = be; }

    const int m0 = blockIdx.y * G1_BM;
    const int n0 = blockIdx.x * G1_BN;
    const int tid  = threadIdx.x;
    const int lane = tid & 31;
    const int warp = tid >> 5;
    const int wm = (warp >> 2) * 32;   // 2 warp-rows over 64 M
    const int wn = (warp & 3) * 32;    // 4 warp-cols over 128 N

    // ldmatrix per-thread source coordinates
    const int aRow = (lane & 7) + ((lane >> 3) & 1) * 8;   // + wm + ms*16
    const int aCol = (lane >> 4) * 8;                      // + kk
    const int bRow = (lane & 7) + ((lane >> 4) & 1) * 8;   // + wn + pair*16
    const int bCol = ((lane >> 3) & 1) * 8;                // + kk

    float acc[2][4][4];
#pragma unroll
    for (int i = 0; i < 2; i++)
#pragma unroll
        for (int j = 0; j < 4; j++)
#pragma unroll
            for (int r = 0; r < 4; r++) acc[i][j][r] = 0.f;

    const int lr = tid >> 3;           // 0..31
    const int lc = (tid & 7) * 8;      // halves within 64-col tile

    const int NITER = IN_DIM / G1_BK;  // 32

    // prologue: stages 0,1
#pragma unroll
    for (int st = 0; st < G1_NS - 1; ++st) {
        const int k0 = st * G1_BK;
        __half* Ab = AsBase + st * G1_STG_A;
        __half* Bb = BsBase + st * G1_STG_B;
#pragma unroll
        for (int i = 0; i < 2; i++) {   // A: 64 rows
            int r = lr + i * 32;
            cpa16(Ab + r * G1_AS + lc, A + (size_t)(m0 + r) * IN_DIM + k0 + lc, 16);
        }
#pragma unroll
        for (int i = 0; i < 4; i++) {   // B: 128 rows
            int r = lr + i * 32;
            cpa16(Bb + r * G1_AS + lc, W + (size_t)(n0 + r) * IN_DIM + k0 + lc, 16);
        }
        cpa_commit();
    }

    for (int it = 0; it < NITER; ++it) {
        cpa_wait1();                   // stage `it` complete (stage it+1 may be in flight)
        __syncthreads();

        if (it + G1_NS - 1 < NITER) {
            const int st = it + G1_NS - 1;
            const int slot = st % G1_NS;
            const int k0 = st * G1_BK;
            __half* Ab = AsBase + slot * G1_STG_A;
            __half* Bb = BsBase + slot * G1_STG_B;
#pragma unroll
            for (int i = 0; i < 2; i++) {
                int r = lr + i * 32;
                cpa16(Ab + r * G1_AS + lc, A + (size_t)(m0 + r) * IN_DIM + k0 + lc, 16);
            }
#pragma unroll
            for (int i = 0; i < 4; i++) {
                int r = lr + i * 32;
                cpa16(Bb + r * G1_AS + lc, W + (size_t)(n0 + r) * IN_DIM + k0 + lc, 16);
            }
            cpa_commit();
        } else {
            cpa_commit();              // keep group counting uniform
        }

        const __half* Ab = AsBase + (it % G1_NS) * G1_STG_A;
        const __half* Bb = BsBase + (it % G1_NS) * G1_STG_B;

#pragma unroll
        for (int kk = 0; kk < G1_BK; kk += 16) {
            uint32_t af[2][4], bf[4][2];
#pragma unroll
            for (int ms = 0; ms < 2; ms++)
                ldsm_x4(af[ms][0], af[ms][1], af[ms][2], af[ms][3],
                        Ab + (wm + ms * 16 + aRow) * G1_AS + kk + aCol);
#pragma unroll
            for (int pr = 0; pr < 2; pr++)
                ldsm_x4(bf[2 * pr][0], bf[2 * pr][1], bf[2 * pr + 1][0], bf[2 * pr + 1][1],
                        Bb + (wn + pr * 16 + bRow) * G1_AS + kk + bCol);
#pragma unroll
            for (int ms = 0; ms < 2; ms++)
#pragma unroll
                for (int ns = 0; ns < 4; ns++)
                    mma_f16(acc[ms][ns], af[ms], bf[ns]);
        }
        __syncthreads();
    }

    // epilogue: + bias. p path -> fp16 g_pembed_h; e path -> fp32 out_e.
#pragma unroll
    for (int ns = 0; ns < 4; ns++) {
        int c0 = n0 + wn + ns * 8 + 2 * (lane & 3);
        float b0v = bias[c0];
        float b1v = bias[c0 + 1];
#pragma unroll
        for (int ms = 0; ms < 2; ms++) {
            int r0 = m0 + wm + ms * 16 + (lane >> 2);
            float2 lo = make_float2(acc[ms][ns][0] + b0v, acc[ms][ns][1] + b1v);
            float2 hi = make_float2(acc[ms][ns][2] + b0v, acc[ms][ns][3] + b1v);
            if (isP) {
                *(uint32_t*)(g_pembed_h + (size_t)r0 * DIM + c0)       = packf16(lo.x, lo.y);
                *(uint32_t*)(g_pembed_h + (size_t)(r0 + 8) * DIM + c0) = packf16(hi.x, hi.y);
            } else {
                *(float2*)(out_e + (size_t)r0 * DIM + c0)       = lo;
                *(float2*)(out_e + (size_t)(r0 + 8) * DIM + c0) = hi;
            }
        }
    }
}

// ---------------- grouped transform (fp16 MMA, W_trans fp32 cvt in-loop) ----------------
// p_t[b,i] = sum_j Wt[a_b][i][j] * p_embed[b][j]
#define T_BM 32
#define T_BN 128
#define T_BK 32
#define T_NS 4
#define T_ASTR 40   // A smem row stride in halves (80B)
#define T_BSTR 40   // B smem row stride in floats (160B: conflict-free float2)
#define T_STG_A (T_BM * T_ASTR)            // halves
#define T_STG_B (T_BN * T_BSTR)            // floats
#define T_SMEM (T_NS * (T_STG_A * 2 + T_STG_B * 4))   // 92160 B

__global__ __launch_bounds__(256) void trans_gemm(const float* __restrict__ Wt,
                                                  float* __restrict__ out)
{
    const int a     = blockIdx.y;
    const int cnt   = g_counts[a];
    const int chunk = blockIdx.z;
    if (chunk * T_BM >= cnt) return;

    const int start  = g_cursor[a] - cnt + chunk * T_BM;
    const int nvalid = min(T_BM, cnt - chunk * T_BM);

    __shared__ int s_ord[T_BM];
    extern __shared__ char tsm[];
    __half* As = (__half*)tsm;                         // [4][32][40]
    float*  Bs = (float*)(tsm + T_NS * T_STG_A * 2);   // [4][128][40]

    const int tid  = threadIdx.x;
    const int lane = tid & 31;
    const int warp = tid >> 5;
    const int wm = (warp >> 2) * 16;   // 2 warp-rows over 32 batches
    const int wn = (warp & 3) * 32;    // 4 warp-cols over 128 dims
    const int i0 = blockIdx.x * T_BN;

    if (tid < T_BM) s_ord[tid] = (tid < nvalid) ? g_order[start + tid] : -1;
    __syncthreads();

    const float* Wa = Wt + (size_t)a * DIM * DIM;

    // A loader: threads 0..127, each owns (row=tid>>2, chunk=(tid&3)*8 halves)
    const int  arow = tid >> 2;
    const int  ach  = (tid & 3) * 8;
    const int  bA   = (tid < 128) ? s_ord[arow] : -1;
    const __half*  srcA0 = (bA >= 0) ? g_pembed_h + (size_t)bA * DIM + ach : g_pembed_h;
    const uint32_t szA   = (bA >= 0) ? 16u : 0u;

    float acc[4][4];
#pragma unroll
    for (int j = 0; j < 4; j++)
#pragma unroll
        for (int r = 0; r < 4; r++) acc[j][r] = 0.f;

    const int NITER = DIM / T_BK;      // 32

    // prologue: stages 0..2
#pragma unroll
    for (int st = 0; st < T_NS - 1; ++st) {
        const int k0 = st * T_BK;
        if (tid < 128)
            cpa16(As + st * T_STG_A + arow * T_ASTR + ach, srcA0 + (szA ? k0 : 0), szA);
#pragma unroll
        for (int i = 0; i < 4; i++) {
            int idx = tid + i * 256;
            int r = idx >> 3, c = (idx & 7) * 4;
            cpa16(Bs + st * T_STG_B + r * T_BSTR + c,
                  Wa + (size_t)(i0 + r) * DIM + k0 + c, 16);
        }
        cpa_commit();
    }

    for (int it = 0; it < NITER; ++it) {
        cpa_wait2();
        __syncthreads();

        if (it + T_NS - 1 < NITER) {
            const int st = it + T_NS - 1;
            const int slot = st & (T_NS - 1);
            const int k0 = st * T_BK;
            if (tid < 128)
                cpa16(As + slot * T_STG_A + arow * T_ASTR + ach, srcA0 + (szA ? k0 : 0), szA);
#pragma unroll
            for (int i = 0; i < 4; i++) {
                int idx = tid + i * 256;
                int r = idx >> 3, c = (idx & 7) * 4;
                cpa16(Bs + slot * T_STG_B + r * T_BSTR + c,
                      Wa + (size_t)(i0 + r) * DIM + k0 + c, 16);
            }
            cpa_commit();
        } else {
            cpa_commit();
        }

        const int buf = it & (T_NS - 1);
        const __half* Ab = As + buf * T_STG_A;
        const float*  Bb = Bs + buf * T_STG_B;
        const int q2 = 2 * (lane & 3);

#pragma unroll
        for (int kk = 0; kk < T_BK; kk += 16) {
            uint32_t af[4], bf[4][2];
            {
                int r = wm + (lane >> 2);
                af[0] = *(const uint32_t*)(Ab + r * T_ASTR + kk + q2);
                af[1] = *(const uint32_t*)(Ab + (r + 8) * T_ASTR + kk + q2);
                af[2] = *(const uint32_t*)(Ab + r * T_ASTR + kk + 8 + q2);
                af[3] = *(const uint32_t*)(Ab + (r + 8) * T_ASTR + kk + 8 + q2);
            }
#pragma unroll
            for (int ns = 0; ns < 4; ns++) {
                int n = wn + ns * 8 + (lane >> 2);
                float2 v0 = *(const float2*)(Bb + n * T_BSTR + kk + q2);
                float2 v1 = *(const float2*)(Bb + n * T_BSTR + kk + 8 + q2);
                bf[ns][0] = packf16(v0.x, v0.y);
                bf[ns][1] = packf16(v1.x, v1.y);
            }
#pragma unroll
            for (int ns = 0; ns < 4; ns++)
                mma_f16(acc[ns], af, bf[ns]);
        }
        __syncthreads();
    }

    // epilogue: scatter to out[b*DIM + i]
    const int rA = wm + (lane >> 2);
    const int b0 = s_ord[rA];
    const int b1 = s_ord[rA + 8];
#pragma unroll
    for (int ns = 0; ns < 4; ns++) {
        int c0 = i0 + wn + ns * 8 + 2 * (lane & 3);
        if (b0 >= 0)
            *(float2*)(out + (size_t)b0 * DIM + c0) = make_float2(acc[ns][0], acc[ns][1]);
        if (b1 >= 0)
            *(float2*)(out + (size_t)b1 * DIM + c0) = make_float2(acc[ns][2], acc[ns][3]);
    }
}

// ---------------- launch ----------------
extern "C" void kernel_launch(void* const* d_in, const int* in_sizes, int n_in,
                              void* d_out, int out_size)
{
    const float* pre = (const float*)d_in[0];
    const float* eff = (const float*)d_in[1];
    const int*   act = (const int*)d_in[2];
    const float* Wp  = (const float*)d_in[3];
    const float* bp  = (const float*)d_in[4];
    const float* We  = (const float*)d_in[5];
    const float* be  = (const float*)d_in[6];
    const float* Wt  = (const float*)d_in[7];

    float* out   = (float*)d_out;              // p_transformed: (B,1,DIM,1)
    float* out_e = out + (size_t)B_SZ * DIM;   // e_embed: (B,DIM)

    cudaFuncSetAttribute(embed_gemm, cudaFuncAttributeMaxDynamicSharedMemorySize, G1_SMEM);
    cudaFuncSetAttribute(trans_gemm, cudaFuncAttributeMaxDynamicSharedMemorySize, T_SMEM);

    group_k<<<1, B_SZ>>>(act);

    wconv_k<<<2 * DIM * IN_DIM / 4 / 256, 256>>>(Wp, We);

    mean_kernel<<<dim3(B_SZ * IN_DIM / 4 / 256, 2), 256>>>(pre, eff);

    embed_gemm<<<dim3(DIM / G1_BN, DIM / G1_BM, 2), 256, G1_SMEM>>>(bp, be, out_e);

    trans_gemm<<<dim3(DIM / T_BN, NACT, B_SZ / T_BM), 256, T_SMEM>>>(Wt, out);
}

// round 8
// speedup vs baseline: 1.4857x; 1.0593x over previous
#include <cuda_runtime.h>
#include <cuda_fp16.h>
#include <cstdint>

#define B_SZ   1024
#define T_SZ   16
#define IN_DIM 2048
#define DIM    1024
#define NACT   64

// ---------------- scratch (no allocations allowed) ----------------
__device__ __align__(16) __half g_pavg_h[B_SZ * IN_DIM];   // 4 MB fp16 means
__device__ __align__(16) __half g_eavg_h[B_SZ * IN_DIM];   // 4 MB
__device__ __align__(16) __half g_wph[DIM * IN_DIM];       // 4 MB fp16 Wp
__device__ __align__(16) __half g_weh[DIM * IN_DIM];       // 4 MB fp16 We
__device__ __align__(16) __half g_pembed_h[B_SZ * DIM];    // 2 MB fp16 p_embed
__device__ int   g_counts[NACT];
__device__ int   g_cursor[NACT];            // group END
__device__ int   g_order[B_SZ];

// ---------------- helpers ----------------
__device__ __forceinline__ uint32_t packf16(float lo, float hi) {
    uint32_t r;
    asm("cvt.rn.f16x2.f32 %0, %1, %2;" : "=r"(r) : "f"(hi), "f"(lo));
    return r;
}

__device__ __forceinline__ void mma_f16(float c[4], const uint32_t a[4], const uint32_t b[2]) {
    asm volatile(
        "mma.sync.aligned.m16n8k16.row.col.f32.f16.f16.f32 "
        "{%0,%1,%2,%3}, {%4,%5,%6,%7}, {%8,%9}, {%0,%1,%2,%3};"
        : "+f"(c[0]), "+f"(c[1]), "+f"(c[2]), "+f"(c[3])
        : "r"(a[0]), "r"(a[1]), "r"(a[2]), "r"(a[3]), "r"(b[0]), "r"(b[1]));
}

__device__ __forceinline__ void ldsm_x4(uint32_t& r0, uint32_t& r1, uint32_t& r2, uint32_t& r3,
                                        const void* p) {
    uint32_t a = (uint32_t)__cvta_generic_to_shared(p);
    asm volatile("ldmatrix.sync.aligned.m8n8.x4.shared.b16 {%0,%1,%2,%3}, [%4];"
                 : "=r"(r0), "=r"(r1), "=r"(r2), "=r"(r3) : "r"(a));
}

__device__ __forceinline__ void cpa16(void* dst, const void* src, uint32_t src_sz) {
    uint32_t d = (uint32_t)__cvta_generic_to_shared(dst);
    asm volatile("cp.async.ca.shared.global [%0], [%1], 16, %2;"
                 :: "r"(d), "l"(src), "r"(src_sz));
}
__device__ __forceinline__ void cpa_commit() { asm volatile("cp.async.commit_group;"); }
__device__ __forceinline__ void cpa_wait1()  { asm volatile("cp.async.wait_group 1;"); }

// ---------------- fused prep: grouping + time-mean + W conversion (one launch) ----------------
// block 0                : group (count+scan+scatter), 256 threads x 4 batches
// blocks 1..4096         : mean (p then e), 2048 blocks each
// blocks 4097..8192      : wconv (Wp then We)
__global__ void prep_k(const int* __restrict__ act,
                       const float* __restrict__ pre, const float* __restrict__ eff,
                       const float* __restrict__ Wp, const float* __restrict__ We)
{
    const int flat = blockIdx.x;
    const int tid  = threadIdx.x;

    if (flat == 0) {
        __shared__ int s_cnt[NACT];
        __shared__ int s_base[NACT];
        if (tid < NACT) s_cnt[tid] = 0;
        __syncthreads();
        int myact[4];
#pragma unroll
        for (int i = 0; i < 4; i++) {
            myact[i] = act[tid + 256 * i];
            atomicAdd(&s_cnt[myact[i]], 1);
        }
        __syncthreads();
        if (tid == 0) {
            int run = 0;
            for (int i = 0; i < NACT; i++) { int c = s_cnt[i]; s_base[i] = run; run += c; }
        }
        __syncthreads();
#pragma unroll
        for (int i = 0; i < 4; i++) {
            int pos = atomicAdd(&s_base[myact[i]], 1);
            g_order[pos] = tid + 256 * i;
        }
        __syncthreads();
        if (tid < NACT) {
            g_counts[tid] = s_cnt[tid];
            g_cursor[tid] = s_base[tid];
        }
        return;
    }

    if (flat <= 4096) {
        // mean
        const int t  = flat - 1;
        const int y  = t >> 11;                    // 0 = pre, 1 = eff
        const int bx = t & 2047;
        const int idx = bx * 256 + tid;            // over B*IN/4
        const float4* src = (const float4*)(y ? eff : pre);
        __half*       dst = y ? g_eavg_h : g_pavg_h;
        const int b  = idx >> 9;
        const int k4 = idx & 511;
        const float4* p = src + (size_t)b * T_SZ * (IN_DIM / 4) + k4;
        float4 s = make_float4(0.f, 0.f, 0.f, 0.f);
#pragma unroll
        for (int tt = 0; tt < T_SZ; tt++) {
            float4 v = p[(size_t)tt * (IN_DIM / 4)];
            s.x += v.x; s.y += v.y; s.z += v.z; s.w += v.w;
        }
        const float inv = 1.0f / T_SZ;
        uint2 o;
        o.x = packf16(s.x * inv, s.y * inv);
        o.y = packf16(s.z * inv, s.w * inv);
        *(uint2*)(dst + (size_t)idx * 4) = o;
        return;
    }

    // wconv
    {
        const int half_n = DIM * IN_DIM / 4;
        const int idx = (flat - 4097) * 256 + tid;
        const float4* src;
        __half* dst;
        int j;
        if (idx < half_n) { src = (const float4*)Wp; dst = g_wph; j = idx; }
        else              { src = (const float4*)We; dst = g_weh; j = idx - half_n; }
        float4 v = src[j];
        uint2 o;
        o.x = packf16(v.x, v.y);
        o.y = packf16(v.z, v.w);
        *(uint2*)(dst + (size_t)j * 4) = o;
    }
}

// ---------------- embedding GEMM (fp16 MMA + ldmatrix): C = A @ W^T + bias ----------------
// 64x128 tile, BK=64 halves, 3-stage cp.async ring, 8 warps 2(M)x4(N), warp 32x32. (R7, measured 37.5us)
#define G1_BM 64
#define G1_BN 128
#define G1_BK 64
#define G1_AS 72
#define G1_STG_A (G1_BM * G1_AS)
#define G1_STG_B (G1_BN * G1_AS)
#define G1_NS 3
#define G1_SMEM ((G1_NS * (G1_STG_A + G1_STG_B)) * 2)   // 82944 B

__global__ __launch_bounds__(256) void embed_gemm(
    const float* __restrict__ bp, const float* __restrict__ be,
    float* __restrict__ out_e)
{
    extern __shared__ __half esm[];
    __half* AsBase = esm;
    __half* BsBase = esm + G1_NS * G1_STG_A;

    const __half *A, *W;
    const float* bias;
    const bool isP = (blockIdx.z == 0);
    if (isP) { A = g_pavg_h; W = g_wph; bias = bp; }
    else     { A = g_eavg_h; W = g_weh; bias = be; }

    const int m0 = blockIdx.y * G1_BM;
    const int n0 = blockIdx.x * G1_BN;
    const int tid  = threadIdx.x;
    const int lane = tid & 31;
    const int warp = tid >> 5;
    const int wm = (warp >> 2) * 32;
    const int wn = (warp & 3) * 32;

    const int aRow = (lane & 7) + ((lane >> 3) & 1) * 8;
    const int aCol = (lane >> 4) * 8;
    const int bRow = (lane & 7) + ((lane >> 4) & 1) * 8;
    const int bCol = ((lane >> 3) & 1) * 8;

    float acc[2][4][4];
#pragma unroll
    for (int i = 0; i < 2; i++)
#pragma unroll
        for (int j = 0; j < 4; j++)
#pragma unroll
            for (int r = 0; r < 4; r++) acc[i][j][r] = 0.f;

    const int lr = tid >> 3;
    const int lc = (tid & 7) * 8;

    const int NITER = IN_DIM / G1_BK;  // 32

#pragma unroll
    for (int st = 0; st < G1_NS - 1; ++st) {
        const int k0 = st * G1_BK;
        __half* Ab = AsBase + st * G1_STG_A;
        __half* Bb = BsBase + st * G1_STG_B;
#pragma unroll
        for (int i = 0; i < 2; i++) {
            int r = lr + i * 32;
            cpa16(Ab + r * G1_AS + lc, A + (size_t)(m0 + r) * IN_DIM + k0 + lc, 16);
        }
#pragma unroll
        for (int i = 0; i < 4; i++) {
            int r = lr + i * 32;
            cpa16(Bb + r * G1_AS + lc, W + (size_t)(n0 + r) * IN_DIM + k0 + lc, 16);
        }
        cpa_commit();
    }

    for (int it = 0; it < NITER; ++it) {
        cpa_wait1();
        __syncthreads();

        if (it + G1_NS - 1 < NITER) {
            const int st = it + G1_NS - 1;
            const int slot = st % G1_NS;
            const int k0 = st * G1_BK;
            __half* Ab = AsBase + slot * G1_STG_A;
            __half* Bb = BsBase + slot * G1_STG_B;
#pragma unroll
            for (int i = 0; i < 2; i++) {
                int r = lr + i * 32;
                cpa16(Ab + r * G1_AS + lc, A + (size_t)(m0 + r) * IN_DIM + k0 + lc, 16);
            }
#pragma unroll
            for (int i = 0; i < 4; i++) {
                int r = lr + i * 32;
                cpa16(Bb + r * G1_AS + lc, W + (size_t)(n0 + r) * IN_DIM + k0 + lc, 16);
            }
            cpa_commit();
        } else {
            cpa_commit();
        }

        const __half* Ab = AsBase + (it % G1_NS) * G1_STG_A;
        const __half* Bb = BsBase + (it % G1_NS) * G1_STG_B;

#pragma unroll
        for (int kk = 0; kk < G1_BK; kk += 16) {
            uint32_t af[2][4], bf[4][2];
#pragma unroll
            for (int ms = 0; ms < 2; ms++)
                ldsm_x4(af[ms][0], af[ms][1], af[ms][2], af[ms][3],
                        Ab + (wm + ms * 16 + aRow) * G1_AS + kk + aCol);
#pragma unroll
            for (int pr = 0; pr < 2; pr++)
                ldsm_x4(bf[2 * pr][0], bf[2 * pr][1], bf[2 * pr + 1][0], bf[2 * pr + 1][1],
                        Bb + (wn + pr * 16 + bRow) * G1_AS + kk + bCol);
#pragma unroll
            for (int ms = 0; ms < 2; ms++)
#pragma unroll
                for (int ns = 0; ns < 4; ns++)
                    mma_f16(acc[ms][ns], af[ms], bf[ns]);
        }
        __syncthreads();
    }

#pragma unroll
    for (int ns = 0; ns < 4; ns++) {
        int c0 = n0 + wn + ns * 8 + 2 * (lane & 3);
        float b0v = bias[c0];
        float b1v = bias[c0 + 1];
#pragma unroll
        for (int ms = 0; ms < 2; ms++) {
            int r0 = m0 + wm + ms * 16 + (lane >> 2);
            float2 lo = make_float2(acc[ms][ns][0] + b0v, acc[ms][ns][1] + b1v);
            float2 hi = make_float2(acc[ms][ns][2] + b0v, acc[ms][ns][3] + b1v);
            if (isP) {
                *(uint32_t*)(g_pembed_h + (size_t)r0 * DIM + c0)       = packf16(lo.x, lo.y);
                *(uint32_t*)(g_pembed_h + (size_t)(r0 + 8) * DIM + c0) = packf16(hi.x, hi.y);
            } else {
                *(float2*)(out_e + (size_t)r0 * DIM + c0)       = lo;
                *(float2*)(out_e + (size_t)(r0 + 8) * DIM + c0) = hi;
            }
        }
    }
}

// ---------------- grouped transform: 2-stage issue-then-wait ring, 46KB smem (4 blocks/SM) ----------------
// p_t[b,i] = sum_j Wt[a_b][i][j] * p_embed[b][j]
#define T_BM 32
#define T_BN 128
#define T_BK 32
#define T_ZD 2      // gridDim.z; in-block chunk loop covers any count
#define T_ASTR 40   // A smem row stride in halves
#define T_BSTR 40   // B smem row stride in floats
#define T_STG_A (T_BM * T_ASTR)            // halves per stage
#define T_STG_B (T_BN * T_BSTR)            // floats per stage
#define T_SMEM (2 * (T_STG_A * 2 + T_STG_B * 4))   // 46080 B

__global__ __launch_bounds__(256) void trans_gemm(const float* __restrict__ Wt,
                                                  float* __restrict__ out)
{
    const int a   = blockIdx.y;
    const int cnt = g_counts[a];
    if (blockIdx.z * T_BM >= cnt) return;
    const int gstart = g_cursor[a] - cnt;

    __shared__ int s_ord[T_BM];
    extern __shared__ char tsm[];
    __half* As = (__half*)tsm;                      // [2][32][40]
    float*  Bs = (float*)(tsm + 2 * T_STG_A * 2);   // [2][128][40]

    const int tid  = threadIdx.x;
    const int lane = tid & 31;
    const int warp = tid >> 5;
    const int wm = (warp >> 2) * 16;   // 2 warp-rows over 32 batches
    const int wn = (warp & 3) * 32;    // 4 warp-cols over 128 dims
    const int i0 = blockIdx.x * T_BN;

    const float* Wa = Wt + (size_t)a * DIM * DIM;
    const int arow = tid >> 2;         // A loader row (threads 0..127)
    const int ach  = (tid & 3) * 8;    // halves
    const int q2   = 2 * (lane & 3);
    const int NITER = DIM / T_BK;      // 32

    for (int chunk = blockIdx.z; chunk * T_BM < cnt; chunk += T_ZD) {
        __syncthreads();               // protect s_ord reuse across chunk iterations
        const int start  = gstart + chunk * T_BM;
        const int nvalid = min(T_BM, cnt - chunk * T_BM);
        if (tid < T_BM) s_ord[tid] = (tid < nvalid) ? g_order[start + tid] : -1;
        __syncthreads();

        const int bA = (tid < 128) ? s_ord[arow] : -1;
        const __half*  srcA0 = (bA >= 0) ? g_pembed_h + (size_t)bA * DIM + ach : g_pembed_h;
        const uint32_t szA   = (bA >= 0) ? 16u : 0u;

        float acc[4][4];
#pragma unroll
        for (int j = 0; j < 4; j++)
#pragma unroll
            for (int r = 0; r < 4; r++) acc[j][r] = 0.f;

        // prologue: stage 0 -> slot 0
        if (tid < 128) cpa16(As + arow * T_ASTR + ach, srcA0, szA);
#pragma unroll
        for (int i = 0; i < 4; i++) {
            int idx = tid + i * 256;
            int r = idx >> 3, c = (idx & 7) * 4;
            cpa16(Bs + r * T_BSTR + c, Wa + (size_t)(i0 + r) * DIM + c, 16);
        }
        cpa_commit();

        for (int it = 0; it < NITER; ++it) {
            // issue next stage first (other slot), then wait for current
            if (it + 1 < NITER) {
                const int slot = (it + 1) & 1;
                const int k0 = (it + 1) * T_BK;
                if (tid < 128)
                    cpa16(As + slot * T_STG_A + arow * T_ASTR + ach, srcA0 + (szA ? k0 : 0), szA);
#pragma unroll
                for (int i = 0; i < 4; i++) {
                    int idx = tid + i * 256;
                    int r = idx >> 3, c = (idx & 7) * 4;
                    cpa16(Bs + slot * T_STG_B + r * T_BSTR + c,
                          Wa + (size_t)(i0 + r) * DIM + k0 + c, 16);
                }
                cpa_commit();
            } else {
                cpa_commit();
            }
            cpa_wait1();               // current stage complete; next may be in flight
            __syncthreads();

            const int buf = it & 1;
            const __half* Ab = As + buf * T_STG_A;
            const float*  Bb = Bs + buf * T_STG_B;

#pragma unroll
            for (int kk = 0; kk < T_BK; kk += 16) {
                uint32_t af[4], bf[4][2];
                {
                    int r = wm + (lane >> 2);
                    af[0] = *(const uint32_t*)(Ab + r * T_ASTR + kk + q2);
                    af[1] = *(const uint32_t*)(Ab + (r + 8) * T_ASTR + kk + q2);
                    af[2] = *(const uint32_t*)(Ab + r * T_ASTR + kk + 8 + q2);
                    af[3] = *(const uint32_t*)(Ab + (r + 8) * T_ASTR + kk + 8 + q2);
                }
#pragma unroll
                for (int ns = 0; ns < 4; ns++) {
                    int n = wn + ns * 8 + (lane >> 2);
                    float2 v0 = *(const float2*)(Bb + n * T_BSTR + kk + q2);
                    float2 v1 = *(const float2*)(Bb + n * T_BSTR + kk + 8 + q2);
                    bf[ns][0] = packf16(v0.x, v0.y);
                    bf[ns][1] = packf16(v1.x, v1.y);
                }
#pragma unroll
                for (int ns = 0; ns < 4; ns++)
                    mma_f16(acc[ns], af, bf[ns]);
            }
            __syncthreads();           // compute done before next iter overwrites this slot
        }

        // epilogue: scatter to out[b*DIM + i]
        const int rA = wm + (lane >> 2);
        const int b0 = s_ord[rA];
        const int b1 = s_ord[rA + 8];
#pragma unroll
        for (int ns = 0; ns < 4; ns++) {
            int c0 = i0 + wn + ns * 8 + 2 * (lane & 3);
            if (b0 >= 0)
                *(float2*)(out + (size_t)b0 * DIM + c0) = make_float2(acc[ns][0], acc[ns][1]);
            if (b1 >= 0)
                *(float2*)(out + (size_t)b1 * DIM + c0) = make_float2(acc[ns][2], acc[ns][3]);
        }
    }
}

// ---------------- launch ----------------
extern "C" void kernel_launch(void* const* d_in, const int* in_sizes, int n_in,
                              void* d_out, int out_size)
{
    const float* pre = (const float*)d_in[0];
    const float* eff = (const float*)d_in[1];
    const int*   act = (const int*)d_in[2];
    const float* Wp  = (const float*)d_in[3];
    const float* bp  = (const float*)d_in[4];
    const float* We  = (const float*)d_in[5];
    const float* be  = (const float*)d_in[6];
    const float* Wt  = (const float*)d_in[7];

    float* out   = (float*)d_out;              // p_transformed: (B,1,DIM,1)
    float* out_e = out + (size_t)B_SZ * DIM;   // e_embed: (B,DIM)

    cudaFuncSetAttribute(embed_gemm, cudaFuncAttributeMaxDynamicSharedMemorySize, G1_SMEM);
    cudaFuncSetAttribute(trans_gemm, cudaFuncAttributeMaxDynamicSharedMemorySize, T_SMEM);

    prep_k<<<8193, 256>>>(act, pre, eff, Wp, We);

    embed_gemm<<<dim3(DIM / G1_BN, DIM / G1_BM, 2), 256, G1_SMEM>>>(bp, be, out_e);

    trans_gemm<<<dim3(DIM / T_BN, NACT, T_ZD), 256, T_SMEM>>>(Wt, out);
}